// round 8
// baseline (speedup 1.0000x reference)
#include <cuda_runtime.h>
#include <cuda_bf16.h>
#include <cstdint>

#define NROWS 1048576
#define DIM   128
#define NSEG  4096

// Scratch (__device__ globals per allocation-free rule)
__device__ float g_xs[NSEG * DIM];                              // segment sums (2 MB)
__device__ float g_xm[NSEG * DIM];                              // xs @ Lambda^T (2 MB)
__device__ __align__(16) __nv_bfloat16 g_xbf[NROWS * DIM];      // x in bf16 (256 MB)
__device__ __align__(16) __nv_bfloat16 g_GbI[DIM * 136];        // Gamma bf16, padded-row image

#define ASTRIDE 136                       // halves per smem row (pad 8)
#define TILE_BYTES (128 * ASTRIDE * 2)    // 34816

__device__ __forceinline__ uint32_t smem_u32(const void* p) {
    uint32_t a;
    asm("{ .reg .u64 t; cvta.to.shared.u64 t, %1; cvt.u32.u64 %0, t; }" : "=r"(a) : "l"(p));
    return a;
}
__device__ __forceinline__ uint32_t pack_bf16x2(float lo, float hi) {
    uint32_t r;
    asm("cvt.rn.bf16x2.f32 %0, %1, %2;" : "=r"(r) : "f"(hi), "f"(lo));
    return r;
}

// ---------------------------------------------------------------------------
// Kernel 0: zero g_xs, build padded-row bf16 image of Gamma [n][k]
// ---------------------------------------------------------------------------
__global__ void k0_init(const float* __restrict__ GW) {
    int idx = blockIdx.x * blockDim.x + threadIdx.x;
    if (idx < NSEG * DIM) g_xs[idx] = 0.0f;
    if (idx < DIM * DIM) {
        int n = idx >> 7, k = idx & 127;
        g_GbI[n * ASTRIDE + k] = __float2bfloat16(GW[idx]);
    }
}

// ---------------------------------------------------------------------------
// Kernel 1: segment sum (sorted ids, run-length regs, boundary atomics)
//           + side-product: write x as bf16 to g_xbf (streamed 8B stores)
// ---------------------------------------------------------------------------
__global__ __launch_bounds__(256) void k1_segsum(const float* __restrict__ x,
                                                 const int* __restrict__ seg) {
    int t = threadIdx.x;
    int stream = t >> 5;
    int c = (t & 31) * 4;
    int base = blockIdx.x * 1024 + stream;

    float4 acc = make_float4(0.f, 0.f, 0.f, 0.f);
    int cur = seg[base];

    #pragma unroll 8
    for (int i = 0; i < 128; i++) {
        int r = base + i * 8;
        int s = seg[r];
        float4 v = *(const float4*)(x + (size_t)r * DIM + c);
        // bf16 side-write (coalesced 8B per lane)
        uint2 pk = make_uint2(pack_bf16x2(v.x, v.y), pack_bf16x2(v.z, v.w));
        *(uint2*)(g_xbf + (size_t)r * DIM + c) = pk;
        if (s != cur) {
            float* d = g_xs + (size_t)cur * DIM + c;
            atomicAdd(d + 0, acc.x); atomicAdd(d + 1, acc.y);
            atomicAdd(d + 2, acc.z); atomicAdd(d + 3, acc.w);
            acc = make_float4(0.f, 0.f, 0.f, 0.f);
            cur = s;
        }
        acc.x += v.x; acc.y += v.y; acc.z += v.z; acc.w += v.w;
    }
    float* d = g_xs + (size_t)cur * DIM + c;
    atomicAdd(d + 0, acc.x); atomicAdd(d + 1, acc.y);
    atomicAdd(d + 2, acc.z); atomicAdd(d + 3, acc.w);
}

// ---------------------------------------------------------------------------
// Kernel 2: g_xm = g_xs @ Lambda_W^T (fp32 exact)
// ---------------------------------------------------------------------------
__global__ __launch_bounds__(128) void k2_xm(const float* __restrict__ LW) {
    extern __shared__ float sm2[];
    float* Lt  = sm2;                 // [128][129]
    float* xss = sm2 + 128 * 129;     // [16][128]
    int t = threadIdx.x;
    int R0 = blockIdx.x * 16;

    for (int i = 0; i < 128; i++) {
        int e = i * 128 + t;
        int j = e >> 7, k = e & 127;
        Lt[k * 129 + j] = LW[e];
    }
    for (int i = 0; i < 16; i++) {
        int e = i * 128 + t;
        int r = e >> 7, k = e & 127;
        xss[r * 128 + k] = g_xs[(size_t)(R0 + r) * DIM + k];
    }
    __syncthreads();

    float acc[16];
    #pragma unroll
    for (int r = 0; r < 16; r++) acc[r] = 0.f;
    for (int k = 0; k < 128; k++) {
        float lv = Lt[k * 129 + t];
        #pragma unroll
        for (int r = 0; r < 16; r++) acc[r] += xss[r * 128 + k] * lv;
    }
    #pragma unroll
    for (int r = 0; r < 16; r++)
        g_xm[(size_t)(R0 + r) * DIM + t] = acc[r];
}

// ---------------------------------------------------------------------------
// Kernel 3: out = x @ Gamma^T (bf16 HMMA) + bias - xm[seg]
// Persistent-ish: 1024 CTAs x 8 tiles of 128 rows. Double-buffered cp.async
// A staging (bf16, no conversion), B staged once per CTA. 8 warps, warp tile
// 32x64. DRAM stays busy: prefetch tile t+1 overlaps MMA+epilogue of tile t.
// ---------------------------------------------------------------------------
#define TILES_PER_CTA 8
#define K3_SMEM (3 * TILE_BYTES)          // B + 2 A buffers = 104448

__global__ __launch_bounds__(256, 2) void k3_main(const int* __restrict__ seg,
                                                  const float* __restrict__ bias,
                                                  float* __restrict__ out) {
    extern __shared__ __nv_bfloat16 sm3[];
    __nv_bfloat16* Bs = sm3;                                  // [128][136]
    uint32_t sbB = smem_u32(Bs);
    uint32_t sbA0 = sbB + TILE_BYTES;

    int tid  = threadIdx.x;
    int warp = tid >> 5;
    int lane = tid & 31;
    int m0 = (warp & 3) * 32;
    int n0 = (warp >> 2) * 64;
    int g  = lane >> 2;
    int t4 = lane & 3;

    // Prologue: stage B (flat copy of padded image) + A tile 0, one group
    #pragma unroll
    for (int i = 0; i < 9; i++) {
        int e = i * 256 + tid;
        if (e < TILE_BYTES / 16)
            asm volatile("cp.async.cg.shared.global [%0], [%1], 16;"
                         :: "r"(sbB + e * 16),
                            "l"((const char*)g_GbI + e * 16) : "memory");
    }
    int tile0 = blockIdx.x * TILES_PER_CTA;
    #pragma unroll
    for (int i = 0; i < 8; i++) {
        int e = i * 256 + tid;
        int row = e >> 4, c16 = e & 15;
        asm volatile("cp.async.cg.shared.global [%0], [%1], 16;"
                     :: "r"(sbA0 + (row * ASTRIDE + c16 * 8) * 2),
                        "l"((const char*)(g_xbf + ((size_t)tile0 * 128 + row) * DIM + c16 * 8))
                     : "memory");
    }
    asm volatile("cp.async.commit_group;" ::: "memory");

    // Loop-invariant: bias regs, fragment offsets
    float2 bias_r[8];
    #pragma unroll
    for (int nt = 0; nt < 8; nt++)
        bias_r[nt] = *(const float2*)(bias + n0 + nt * 8 + 2 * t4);

    uint32_t aoff[2];   // smem byte offsets within an A buffer for the 2 m-tiles
    #pragma unroll
    for (int mt = 0; mt < 2; mt++)
        aoff[mt] = ((m0 + mt * 16 + (lane & 15)) * ASTRIDE + ((lane >> 4) << 3)) * 2;
    uint32_t boff = ((n0 + (lane & 7) + ((lane >> 4) << 3)) * ASTRIDE
                     + (((lane >> 3) & 1) << 3)) * 2;

    #pragma unroll 1
    for (int t = 0; t < TILES_PER_CTA; t++) {
        int tile = tile0 + t;
        int r0 = tile * 128;
        uint32_t sbA = sbA0 + (t & 1) * TILE_BYTES;

        // Prefetch next A tile into the other buffer
        if (t < TILES_PER_CTA - 1) {
            uint32_t sbN = sbA0 + ((t + 1) & 1) * TILE_BYTES;
            const __nv_bfloat16* src = g_xbf + (size_t)(r0 + 128) * DIM;
            #pragma unroll
            for (int i = 0; i < 8; i++) {
                int e = i * 256 + tid;
                int row = e >> 4, c16 = e & 15;
                asm volatile("cp.async.cg.shared.global [%0], [%1], 16;"
                             :: "r"(sbN + (row * ASTRIDE + c16 * 8) * 2),
                                "l"((const char*)(src + (size_t)row * DIM + c16 * 8))
                             : "memory");
            }
            asm volatile("cp.async.commit_group;" ::: "memory");
            asm volatile("cp.async.wait_group 1;" ::: "memory");
        } else {
            asm volatile("cp.async.wait_group 0;" ::: "memory");
        }
        __syncthreads();    // A[t] (and B) visible to all warps

        // Epilogue seg ids early (latency hidden under MMA)
        int sa[2], sb2[2];
        #pragma unroll
        for (int mt = 0; mt < 2; mt++) {
            int ra = r0 + m0 + mt * 16 + g;
            sa[mt]  = seg[ra];
            sb2[mt] = seg[ra + 8];
        }

        float acc[2][8][4];
        #pragma unroll
        for (int mt = 0; mt < 2; mt++)
            #pragma unroll
            for (int nt = 0; nt < 8; nt++)
                #pragma unroll
                for (int q = 0; q < 4; q++) acc[mt][nt][q] = 0.f;

        #pragma unroll
        for (int ks = 0; ks < 8; ks++) {
            uint32_t a[2][4], b[4][4];
            #pragma unroll
            for (int mt = 0; mt < 2; mt++) {
                asm volatile(
                    "ldmatrix.sync.aligned.m8n8.x4.shared.b16 {%0,%1,%2,%3}, [%4];"
                    : "=r"(a[mt][0]), "=r"(a[mt][1]), "=r"(a[mt][2]), "=r"(a[mt][3])
                    : "r"(sbA + aoff[mt] + ks * 32));
            }
            #pragma unroll
            for (int np = 0; np < 4; np++) {
                asm volatile(
                    "ldmatrix.sync.aligned.m8n8.x4.shared.b16 {%0,%1,%2,%3}, [%4];"
                    : "=r"(b[np][0]), "=r"(b[np][1]), "=r"(b[np][2]), "=r"(b[np][3])
                    : "r"(sbB + boff + (np * 16 * ASTRIDE) * 2 + ks * 32));
            }
            #pragma unroll
            for (int mt = 0; mt < 2; mt++)
                #pragma unroll
                for (int np = 0; np < 4; np++) {
                    asm volatile(
                        "mma.sync.aligned.m16n8k16.row.col.f32.bf16.bf16.f32 "
                        "{%0,%1,%2,%3}, {%4,%5,%6,%7}, {%8,%9}, {%0,%1,%2,%3};\n"
                        : "+f"(acc[mt][2 * np][0]), "+f"(acc[mt][2 * np][1]),
                          "+f"(acc[mt][2 * np][2]), "+f"(acc[mt][2 * np][3])
                        : "r"(a[mt][0]), "r"(a[mt][1]), "r"(a[mt][2]), "r"(a[mt][3]),
                          "r"(b[np][0]), "r"(b[np][1]));
                    asm volatile(
                        "mma.sync.aligned.m16n8k16.row.col.f32.bf16.bf16.f32 "
                        "{%0,%1,%2,%3}, {%4,%5,%6,%7}, {%8,%9}, {%0,%1,%2,%3};\n"
                        : "+f"(acc[mt][2 * np + 1][0]), "+f"(acc[mt][2 * np + 1][1]),
                          "+f"(acc[mt][2 * np + 1][2]), "+f"(acc[mt][2 * np + 1][3])
                        : "r"(a[mt][0]), "r"(a[mt][1]), "r"(a[mt][2]), "r"(a[mt][3]),
                          "r"(b[np][2]), "r"(b[np][3]));
                }
        }

        // Epilogue: + bias - xm[seg]; sector-aligned float2 stores
        #pragma unroll
        for (int mt = 0; mt < 2; mt++) {
            const float* xa = g_xm + (size_t)sa[mt] * DIM;
            const float* xb = g_xm + (size_t)sb2[mt] * DIM;
            int ra = r0 + m0 + mt * 16 + g;
            int rb = ra + 8;
            #pragma unroll
            for (int nt = 0; nt < 8; nt++) {
                int j = n0 + nt * 8 + 2 * t4;
                float2 ma = *(const float2*)(xa + j);
                float2 mb = *(const float2*)(xb + j);
                float2 oa, ob;
                oa.x = acc[mt][nt][0] + bias_r[nt].x - ma.x;
                oa.y = acc[mt][nt][1] + bias_r[nt].y - ma.y;
                ob.x = acc[mt][nt][2] + bias_r[nt].x - mb.x;
                ob.y = acc[mt][nt][3] + bias_r[nt].y - mb.y;
                *(float2*)(out + (size_t)ra * DIM + j) = oa;
                *(float2*)(out + (size_t)rb * DIM + j) = ob;
            }
        }
        __syncthreads();    // all reads of A[t] done before next prefetch overwrites
    }
}

// ---------------------------------------------------------------------------
extern "C" void kernel_launch(void* const* d_in, const int* in_sizes, int n_in,
                              void* d_out, int out_size) {
    const float* x   = (const float*)d_in[0];
    const int*   seg = (const int*)d_in[1];
    const float* GW = nullptr;
    const float* Gb = nullptr;
    const float* LW = nullptr;
    for (int i = 2; i < n_in; i++) {
        int s = in_sizes[i];
        if (s == DIM * DIM) { if (!GW) GW = (const float*)d_in[i]; else LW = (const float*)d_in[i]; }
        else if (s == DIM) { Gb = (const float*)d_in[i]; }
    }
    float* out = (float*)d_out;

    cudaFuncSetAttribute(k2_xm,   cudaFuncAttributeMaxDynamicSharedMemorySize, 74240);
    cudaFuncSetAttribute(k3_main, cudaFuncAttributeMaxDynamicSharedMemorySize, K3_SMEM);

    k0_init<<<2048, 256>>>(GW);
    k1_segsum<<<NROWS / 1024, 256>>>(x, seg);
    k2_xm<<<NSEG / 16, 128, 74240>>>(LW);
    k3_main<<<NROWS / (128 * TILES_PER_CTA), 256, K3_SMEM>>>(seg, Gb, out);
}

// round 9
// speedup vs baseline: 1.0310x; 1.0310x over previous
#include <cuda_runtime.h>
#include <cuda_bf16.h>
#include <cstdint>

#define NROWS 1048576
#define DIM   128
#define NSEG  4096

// Scratch (__device__ globals per allocation-free rule)
__device__ float g_xs[NSEG * DIM];                          // segment sums (2 MB)
__device__ float g_xm[NSEG * DIM];                          // xs @ Lambda^T (2 MB)
__device__ __align__(16) __nv_bfloat16 g_GbI[DIM * 136];    // Gamma bf16, padded-row image

#define ASTRIDE 136                         // halves per smem row (pad 8)
#define BTILE_BYTES (128 * ASTRIDE * 2)     // 34816
#define ATILE_BYTES (64 * ASTRIDE * 2)      // 17408
#define K3_SMEM (BTILE_BYTES + ATILE_BYTES) // 52224 -> 4 CTAs/SM

__device__ __forceinline__ uint32_t smem_u32(const void* p) {
    uint32_t a;
    asm("{ .reg .u64 t; cvta.to.shared.u64 t, %1; cvt.u32.u64 %0, t; }" : "=r"(a) : "l"(p));
    return a;
}
__device__ __forceinline__ uint32_t pack_bf16x2(float lo, float hi) {
    uint32_t r;
    asm("cvt.rn.bf16x2.f32 %0, %1, %2;" : "=r"(r) : "f"(hi), "f"(lo));
    return r;
}

// ---------------------------------------------------------------------------
// Kernel 0: zero g_xs, build padded-row bf16 image of Gamma [n][k]
// ---------------------------------------------------------------------------
__global__ void k0_init(const float* __restrict__ GW) {
    int idx = blockIdx.x * blockDim.x + threadIdx.x;
    if (idx < NSEG * DIM) g_xs[idx] = 0.0f;
    if (idx < DIM * DIM) {
        int n = idx >> 7, k = idx & 127;
        g_GbI[n * ASTRIDE + k] = __float2bfloat16(GW[idx]);
    }
}

// ---------------------------------------------------------------------------
// Kernel 1: segment sum (sorted ids, run-length regs, boundary atomics)
// (reverted to R6: pure fp32 streaming read, no side-writes)
// ---------------------------------------------------------------------------
__global__ __launch_bounds__(256) void k1_segsum(const float* __restrict__ x,
                                                 const int* __restrict__ seg) {
    int t = threadIdx.x;
    int stream = t >> 5;
    int c = (t & 31) * 4;
    int base = blockIdx.x * 1024 + stream;

    float4 acc = make_float4(0.f, 0.f, 0.f, 0.f);
    int cur = seg[base];

    #pragma unroll 8
    for (int i = 0; i < 128; i++) {
        int r = base + i * 8;
        int s = seg[r];
        float4 v = *(const float4*)(x + (size_t)r * DIM + c);
        if (s != cur) {
            float* d = g_xs + (size_t)cur * DIM + c;
            atomicAdd(d + 0, acc.x); atomicAdd(d + 1, acc.y);
            atomicAdd(d + 2, acc.z); atomicAdd(d + 3, acc.w);
            acc = make_float4(0.f, 0.f, 0.f, 0.f);
            cur = s;
        }
        acc.x += v.x; acc.y += v.y; acc.z += v.z; acc.w += v.w;
    }
    float* d = g_xs + (size_t)cur * DIM + c;
    atomicAdd(d + 0, acc.x); atomicAdd(d + 1, acc.y);
    atomicAdd(d + 2, acc.z); atomicAdd(d + 3, acc.w);
}

// ---------------------------------------------------------------------------
// Kernel 2: g_xm = g_xs @ Lambda_W^T (fp32 exact)
// ---------------------------------------------------------------------------
__global__ __launch_bounds__(128) void k2_xm(const float* __restrict__ LW) {
    extern __shared__ float sm2[];
    float* Lt  = sm2;                 // [128][129]
    float* xss = sm2 + 128 * 129;     // [16][128]
    int t = threadIdx.x;
    int R0 = blockIdx.x * 16;

    for (int i = 0; i < 128; i++) {
        int e = i * 128 + t;
        int j = e >> 7, k = e & 127;
        Lt[k * 129 + j] = LW[e];
    }
    for (int i = 0; i < 16; i++) {
        int e = i * 128 + t;
        int r = e >> 7, k = e & 127;
        xss[r * 128 + k] = g_xs[(size_t)(R0 + r) * DIM + k];
    }
    __syncthreads();

    float acc[16];
    #pragma unroll
    for (int r = 0; r < 16; r++) acc[r] = 0.f;
    for (int k = 0; k < 128; k++) {
        float lv = Lt[k * 129 + t];
        #pragma unroll
        for (int r = 0; r < 16; r++) acc[r] += xss[r * 128 + k] * lv;
    }
    #pragma unroll
    for (int r = 0; r < 16; r++)
        g_xm[(size_t)(R0 + r) * DIM + t] = acc[r];
}

// ---------------------------------------------------------------------------
// Kernel 3: out = x @ Gamma^T (bf16 HMMA) + bias - xm[seg]
// 128 threads = 4 warps; block tile 64x128; warp tile 32x64.
// smem 52 KB, regs <=128 -> 4 CTAs/SM: cross-CTA phase overlap keeps DRAM
// busy during each CTA's MMA/epilogue phase (the R6 limiter).
// ---------------------------------------------------------------------------
__global__ __launch_bounds__(128, 4) void k3_main(const float* __restrict__ x,
                                                  const int* __restrict__ seg,
                                                  const float* __restrict__ bias,
                                                  float* __restrict__ out) {
    extern __shared__ __nv_bfloat16 sm3[];
    __nv_bfloat16* Bs = sm3;                          // [128][136]  Bs[n][k]
    __nv_bfloat16* As = sm3 + 128 * ASTRIDE;          // [64][136]
    uint32_t sbB = smem_u32(Bs);
    uint32_t sbA = smem_u32(As);

    int tid  = threadIdx.x;
    int warp = tid >> 5;
    int lane = tid & 31;
    int r0 = blockIdx.x * 64;
    int m0 = (warp & 1) * 32;
    int n0 = (warp >> 1) * 64;

    // Stage B via flat cp.async of padded image (34816 B = 2176 chunks, 17/thr)
    #pragma unroll
    for (int i = 0; i < 17; i++) {
        int e = i * 128 + tid;
        asm volatile("cp.async.cg.shared.global [%0], [%1], 16;"
                     :: "r"(sbB + e * 16),
                        "l"((const char*)g_GbI + e * 16) : "memory");
    }
    asm volatile("cp.async.commit_group;" ::: "memory");

    // Stage A: LDG fp32 -> bf16 -> STS.128 (64 rows x 16 chunks, 8/thr)
    #pragma unroll
    for (int i = 0; i < 8; i++) {
        int e = i * 128 + tid;
        int row = e >> 4, g2 = e & 15;
        const float4* src = (const float4*)(x + (size_t)(r0 + row) * DIM + g2 * 8);
        float4 v0 = src[0], v1 = src[1];
        uint32_t p0 = pack_bf16x2(v0.x, v0.y);
        uint32_t p1 = pack_bf16x2(v0.z, v0.w);
        uint32_t p2 = pack_bf16x2(v1.x, v1.y);
        uint32_t p3 = pack_bf16x2(v1.z, v1.w);
        asm volatile("st.shared.v4.b32 [%0], {%1,%2,%3,%4};"
                     :: "r"(sbA + (row * ASTRIDE + g2 * 8) * 2),
                        "r"(p0), "r"(p1), "r"(p2), "r"(p3) : "memory");
    }

    // Prefetch epilogue seg ids (2 rows/lane)
    int g  = lane >> 2;
    int t4 = lane & 3;
    int sa[2], sb2[2];
    #pragma unroll
    for (int mt = 0; mt < 2; mt++) {
        int ra = r0 + m0 + mt * 16 + g;
        sa[mt]  = seg[ra];
        sb2[mt] = seg[ra + 8];
    }

    asm volatile("cp.async.wait_group 0;" ::: "memory");
    __syncthreads();

    // Fragment base addresses
    uint32_t aoff[2];
    #pragma unroll
    for (int mt = 0; mt < 2; mt++)
        aoff[mt] = sbA + ((m0 + mt * 16 + (lane & 15)) * ASTRIDE + ((lane >> 4) << 3)) * 2;
    uint32_t boff = sbB + ((n0 + (lane & 7) + ((lane >> 4) << 3)) * ASTRIDE
                           + (((lane >> 3) & 1) << 3)) * 2;

    float acc[2][8][4];
    #pragma unroll
    for (int mt = 0; mt < 2; mt++)
        #pragma unroll
        for (int nt = 0; nt < 8; nt++)
            #pragma unroll
            for (int q = 0; q < 4; q++) acc[mt][nt][q] = 0.f;

    #pragma unroll
    for (int ks = 0; ks < 8; ks++) {
        uint32_t a[2][4], b[4][4];
        #pragma unroll
        for (int mt = 0; mt < 2; mt++) {
            asm volatile(
                "ldmatrix.sync.aligned.m8n8.x4.shared.b16 {%0,%1,%2,%3}, [%4];"
                : "=r"(a[mt][0]), "=r"(a[mt][1]), "=r"(a[mt][2]), "=r"(a[mt][3])
                : "r"(aoff[mt] + ks * 32));
        }
        #pragma unroll
        for (int np = 0; np < 4; np++) {
            asm volatile(
                "ldmatrix.sync.aligned.m8n8.x4.shared.b16 {%0,%1,%2,%3}, [%4];"
                : "=r"(b[np][0]), "=r"(b[np][1]), "=r"(b[np][2]), "=r"(b[np][3])
                : "r"(boff + (np * 16 * ASTRIDE) * 2 + ks * 32));
        }
        #pragma unroll
        for (int mt = 0; mt < 2; mt++)
            #pragma unroll
            for (int np = 0; np < 4; np++) {
                asm volatile(
                    "mma.sync.aligned.m16n8k16.row.col.f32.bf16.bf16.f32 "
                    "{%0,%1,%2,%3}, {%4,%5,%6,%7}, {%8,%9}, {%0,%1,%2,%3};\n"
                    : "+f"(acc[mt][2 * np][0]), "+f"(acc[mt][2 * np][1]),
                      "+f"(acc[mt][2 * np][2]), "+f"(acc[mt][2 * np][3])
                    : "r"(a[mt][0]), "r"(a[mt][1]), "r"(a[mt][2]), "r"(a[mt][3]),
                      "r"(b[np][0]), "r"(b[np][1]));
                asm volatile(
                    "mma.sync.aligned.m16n8k16.row.col.f32.bf16.bf16.f32 "
                    "{%0,%1,%2,%3}, {%4,%5,%6,%7}, {%8,%9}, {%0,%1,%2,%3};\n"
                    : "+f"(acc[mt][2 * np + 1][0]), "+f"(acc[mt][2 * np + 1][1]),
                      "+f"(acc[mt][2 * np + 1][2]), "+f"(acc[mt][2 * np + 1][3])
                    : "r"(a[mt][0]), "r"(a[mt][1]), "r"(a[mt][2]), "r"(a[mt][3]),
                      "r"(b[np][2]), "r"(b[np][3]));
            }
    }

    // Epilogue: + bias - xm[seg]; sector-aligned float2 stores
    float2 bias_r[8];
    #pragma unroll
    for (int nt = 0; nt < 8; nt++)
        bias_r[nt] = *(const float2*)(bias + n0 + nt * 8 + 2 * t4);

    #pragma unroll
    for (int mt = 0; mt < 2; mt++) {
        const float* xa = g_xm + (size_t)sa[mt] * DIM;
        const float* xb = g_xm + (size_t)sb2[mt] * DIM;
        int ra = r0 + m0 + mt * 16 + g;
        int rb = ra + 8;
        #pragma unroll
        for (int nt = 0; nt < 8; nt++) {
            int j = n0 + nt * 8 + 2 * t4;
            float2 ma = *(const float2*)(xa + j);
            float2 mb = *(const float2*)(xb + j);
            float2 oa, ob;
            oa.x = acc[mt][nt][0] + bias_r[nt].x - ma.x;
            oa.y = acc[mt][nt][1] + bias_r[nt].y - ma.y;
            ob.x = acc[mt][nt][2] + bias_r[nt].x - mb.x;
            ob.y = acc[mt][nt][3] + bias_r[nt].y - mb.y;
            *(float2*)(out + (size_t)ra * DIM + j) = oa;
            *(float2*)(out + (size_t)rb * DIM + j) = ob;
        }
    }
}

// ---------------------------------------------------------------------------
extern "C" void kernel_launch(void* const* d_in, const int* in_sizes, int n_in,
                              void* d_out, int out_size) {
    const float* x   = (const float*)d_in[0];
    const int*   seg = (const int*)d_in[1];
    const float* GW = nullptr;
    const float* Gb = nullptr;
    const float* LW = nullptr;
    for (int i = 2; i < n_in; i++) {
        int s = in_sizes[i];
        if (s == DIM * DIM) { if (!GW) GW = (const float*)d_in[i]; else LW = (const float*)d_in[i]; }
        else if (s == DIM) { Gb = (const float*)d_in[i]; }
    }
    float* out = (float*)d_out;

    cudaFuncSetAttribute(k2_xm,   cudaFuncAttributeMaxDynamicSharedMemorySize, 74240);
    cudaFuncSetAttribute(k3_main, cudaFuncAttributeMaxDynamicSharedMemorySize, K3_SMEM);

    k0_init<<<2048, 256>>>(GW);
    k1_segsum<<<NROWS / 1024, 256>>>(x, seg);
    k2_xm<<<NSEG / 16, 128, 74240>>>(LW);
    k3_main<<<NROWS / 64, 128, K3_SMEM>>>(x, seg, Gb, out);
}

// round 10
// speedup vs baseline: 1.0810x; 1.0485x over previous
#include <cuda_runtime.h>
#include <cuda_bf16.h>
#include <cstdint>

#define NROWS 1048576
#define DIM   128
#define NSEG  4096

// Scratch (__device__ globals per allocation-free rule)
__device__ float g_xs[NSEG * DIM];                          // segment sums (2 MB)
__device__ float g_xm[NSEG * DIM];                          // xs @ Lambda^T (2 MB)
__device__ __align__(16) __nv_bfloat16 g_GbI[DIM * 136];    // Gamma bf16, padded-row image

#define ASTRIDE 136                         // halves per smem B row (pad 8)
#define BTILE_BYTES (128 * ASTRIDE * 2)     // 34816
#define K3_SMEM BTILE_BYTES

__device__ __forceinline__ uint32_t smem_u32(const void* p) {
    uint32_t a;
    asm("{ .reg .u64 t; cvta.to.shared.u64 t, %1; cvt.u32.u64 %0, t; }" : "=r"(a) : "l"(p));
    return a;
}
__device__ __forceinline__ uint32_t pack_bf16x2(float lo, float hi) {
    uint32_t r;
    asm("cvt.rn.bf16x2.f32 %0, %1, %2;" : "=r"(r) : "f"(hi), "f"(lo));
    return r;
}
__device__ __forceinline__ float2 ldcs_f2(const float* p) {
    float2 v;
    asm volatile("ld.global.cs.v2.f32 {%0,%1}, [%2];" : "=f"(v.x), "=f"(v.y) : "l"(p));
    return v;
}
__device__ __forceinline__ float4 ldcs_f4(const float* p) {
    float4 v;
    asm volatile("ld.global.cs.v4.f32 {%0,%1,%2,%3}, [%4];"
                 : "=f"(v.x), "=f"(v.y), "=f"(v.z), "=f"(v.w) : "l"(p));
    return v;
}
__device__ __forceinline__ void stcs_f2(float* p, float2 v) {
    asm volatile("st.global.cs.v2.f32 [%0], {%1,%2};" :: "l"(p), "f"(v.x), "f"(v.y) : "memory");
}

// ---------------------------------------------------------------------------
// Kernel 0: zero g_xs, build padded-row bf16 image of Gamma [n][k]
// ---------------------------------------------------------------------------
__global__ void k0_init(const float* __restrict__ GW) {
    int idx = blockIdx.x * blockDim.x + threadIdx.x;
    if (idx < NSEG * DIM) g_xs[idx] = 0.0f;
    if (idx < DIM * DIM) {
        int n = idx >> 7, k = idx & 127;
        g_GbI[n * ASTRIDE + k] = __float2bfloat16(GW[idx]);
    }
}

// ---------------------------------------------------------------------------
// Kernel 1: segment sum (sorted ids, run-length regs, boundary atomics)
// x loads use .cs (stream-through, keep L2 for hot data)
// ---------------------------------------------------------------------------
__global__ __launch_bounds__(256) void k1_segsum(const float* __restrict__ x,
                                                 const int* __restrict__ seg) {
    int t = threadIdx.x;
    int stream = t >> 5;
    int c = (t & 31) * 4;
    int base = blockIdx.x * 1024 + stream;

    float4 acc = make_float4(0.f, 0.f, 0.f, 0.f);
    int cur = seg[base];

    #pragma unroll 8
    for (int i = 0; i < 128; i++) {
        int r = base + i * 8;
        int s = seg[r];
        float4 v = ldcs_f4(x + (size_t)r * DIM + c);
        if (s != cur) {
            float* d = g_xs + (size_t)cur * DIM + c;
            atomicAdd(d + 0, acc.x); atomicAdd(d + 1, acc.y);
            atomicAdd(d + 2, acc.z); atomicAdd(d + 3, acc.w);
            acc = make_float4(0.f, 0.f, 0.f, 0.f);
            cur = s;
        }
        acc.x += v.x; acc.y += v.y; acc.z += v.z; acc.w += v.w;
    }
    float* d = g_xs + (size_t)cur * DIM + c;
    atomicAdd(d + 0, acc.x); atomicAdd(d + 1, acc.y);
    atomicAdd(d + 2, acc.z); atomicAdd(d + 3, acc.w);
}

// ---------------------------------------------------------------------------
// Kernel 2: g_xm = g_xs @ Lambda_W^T (fp32 exact)
// ---------------------------------------------------------------------------
__global__ __launch_bounds__(128) void k2_xm(const float* __restrict__ LW) {
    extern __shared__ float sm2[];
    float* Lt  = sm2;                 // [128][129]
    float* xss = sm2 + 128 * 129;     // [16][128]
    int t = threadIdx.x;
    int R0 = blockIdx.x * 16;

    for (int i = 0; i < 128; i++) {
        int e = i * 128 + t;
        int j = e >> 7, k = e & 127;
        Lt[k * 129 + j] = LW[e];
    }
    for (int i = 0; i < 16; i++) {
        int e = i * 128 + t;
        int r = e >> 7, k = e & 127;
        xss[r * 128 + k] = g_xs[(size_t)(R0 + r) * DIM + k];
    }
    __syncthreads();

    float acc[16];
    #pragma unroll
    for (int r = 0; r < 16; r++) acc[r] = 0.f;
    for (int k = 0; k < 128; k++) {
        float lv = Lt[k * 129 + t];
        #pragma unroll
        for (int r = 0; r < 16; r++) acc[r] += xss[r * 128 + k] * lv;
    }
    #pragma unroll
    for (int r = 0; r < 16; r++)
        g_xm[(size_t)(R0 + r) * DIM + t] = acc[r];
}

// ---------------------------------------------------------------------------
// Kernel 3: out = x @ Gamma^T (bf16 HMMA) + bias - xm[seg]
// A fragments loaded DIRECTLY from gmem (float2 per fragment half, .cs) and
// packed to bf16 in regs -- no A smem, no staging barrier, no phase structure.
// B (Gamma) staged once per CTA into smem. 256 thr = 8 warps of 32x64 tiles.
// Only one __syncthreads (after B stage); warps then stream freely.
// ---------------------------------------------------------------------------
__global__ __launch_bounds__(256, 2) void k3_main(const float* __restrict__ x,
                                                  const int* __restrict__ seg,
                                                  const float* __restrict__ bias,
                                                  float* __restrict__ out) {
    extern __shared__ __nv_bfloat16 sm3[];
    __nv_bfloat16* Bs = sm3;                          // [128][136]  Bs[n][k]
    uint32_t sbB = smem_u32(Bs);

    int tid  = threadIdx.x;
    int warp = tid >> 5;
    int lane = tid & 31;
    int r0 = blockIdx.x * 128;
    int m0 = (warp & 3) * 32;
    int n0 = (warp >> 2) * 64;
    int g  = lane >> 2;
    int t4 = lane & 3;

    // Stage B via flat cp.async of padded image (2176 chunks over 256 thr)
    #pragma unroll
    for (int i = 0; i < 9; i++) {
        int e = i * 256 + tid;
        if (e < BTILE_BYTES / 16)
            asm volatile("cp.async.cg.shared.global [%0], [%1], 16;"
                         :: "r"(sbB + e * 16),
                            "l"((const char*)g_GbI + e * 16) : "memory");
    }
    asm volatile("cp.async.commit_group;" ::: "memory");

    // Epilogue seg ids (issued before the long compute; latency hidden)
    int sa[2], sb2[2];
    #pragma unroll
    for (int mt = 0; mt < 2; mt++) {
        int ra = r0 + m0 + mt * 16 + g;
        sa[mt]  = seg[ra];
        sb2[mt] = seg[ra + 8];
    }
    float2 bias_r[8];
    #pragma unroll
    for (int nt = 0; nt < 8; nt++)
        bias_r[nt] = *(const float2*)(bias + n0 + nt * 8 + 2 * t4);

    // Per-lane A row pointers: (mt, row g / row g+8)
    const float* pa[2][2];
    #pragma unroll
    for (int mt = 0; mt < 2; mt++) {
        pa[mt][0] = x + (size_t)(r0 + m0 + mt * 16 + g) * DIM + 2 * t4;
        pa[mt][1] = pa[mt][0] + 8 * DIM;
    }

    asm volatile("cp.async.wait_group 0;" ::: "memory");
    __syncthreads();

    uint32_t boff = sbB + ((n0 + (lane & 7) + ((lane >> 4) << 3)) * ASTRIDE
                           + (((lane >> 3) & 1) << 3)) * 2;

    float acc[2][8][4];
    #pragma unroll
    for (int mt = 0; mt < 2; mt++)
        #pragma unroll
        for (int nt = 0; nt < 8; nt++)
            #pragma unroll
            for (int q = 0; q < 4; q++) acc[mt][nt][q] = 0.f;

    #pragma unroll
    for (int ks = 0; ks < 8; ks++) {
        // A fragments straight from gmem: 4 float2 per (mt); pack to bf16x2
        uint32_t a[2][4];
        #pragma unroll
        for (int mt = 0; mt < 2; mt++) {
            float2 v0 = ldcs_f2(pa[mt][0] + ks * 16);        // row g,   k..k+1
            float2 v1 = ldcs_f2(pa[mt][1] + ks * 16);        // row g+8, k..k+1
            float2 v2 = ldcs_f2(pa[mt][0] + ks * 16 + 8);    // row g,   k+8..k+9
            float2 v3 = ldcs_f2(pa[mt][1] + ks * 16 + 8);    // row g+8, k+8..k+9
            a[mt][0] = pack_bf16x2(v0.x, v0.y);
            a[mt][1] = pack_bf16x2(v1.x, v1.y);
            a[mt][2] = pack_bf16x2(v2.x, v2.y);
            a[mt][3] = pack_bf16x2(v3.x, v3.y);
        }
        uint32_t b[4][4];
        #pragma unroll
        for (int np = 0; np < 4; np++) {
            asm volatile(
                "ldmatrix.sync.aligned.m8n8.x4.shared.b16 {%0,%1,%2,%3}, [%4];"
                : "=r"(b[np][0]), "=r"(b[np][1]), "=r"(b[np][2]), "=r"(b[np][3])
                : "r"(boff + (np * 16 * ASTRIDE) * 2 + ks * 32));
        }
        #pragma unroll
        for (int mt = 0; mt < 2; mt++)
            #pragma unroll
            for (int np = 0; np < 4; np++) {
                asm volatile(
                    "mma.sync.aligned.m16n8k16.row.col.f32.bf16.bf16.f32 "
                    "{%0,%1,%2,%3}, {%4,%5,%6,%7}, {%8,%9}, {%0,%1,%2,%3};\n"
                    : "+f"(acc[mt][2 * np][0]), "+f"(acc[mt][2 * np][1]),
                      "+f"(acc[mt][2 * np][2]), "+f"(acc[mt][2 * np][3])
                    : "r"(a[mt][0]), "r"(a[mt][1]), "r"(a[mt][2]), "r"(a[mt][3]),
                      "r"(b[np][0]), "r"(b[np][1]));
                asm volatile(
                    "mma.sync.aligned.m16n8k16.row.col.f32.bf16.bf16.f32 "
                    "{%0,%1,%2,%3}, {%4,%5,%6,%7}, {%8,%9}, {%0,%1,%2,%3};\n"
                    : "+f"(acc[mt][2 * np + 1][0]), "+f"(acc[mt][2 * np + 1][1]),
                      "+f"(acc[mt][2 * np + 1][2]), "+f"(acc[mt][2 * np + 1][3])
                    : "r"(a[mt][0]), "r"(a[mt][1]), "r"(a[mt][2]), "r"(a[mt][3]),
                      "r"(b[np][2]), "r"(b[np][3]));
            }
    }

    // Epilogue: + bias - xm[seg]; sector-aligned .cs float2 stores
    #pragma unroll
    for (int mt = 0; mt < 2; mt++) {
        const float* xa = g_xm + (size_t)sa[mt] * DIM;
        const float* xb = g_xm + (size_t)sb2[mt] * DIM;
        int ra = r0 + m0 + mt * 16 + g;
        int rb = ra + 8;
        #pragma unroll
        for (int nt = 0; nt < 8; nt++) {
            int j = n0 + nt * 8 + 2 * t4;
            float2 ma = *(const float2*)(xa + j);
            float2 mb = *(const float2*)(xb + j);
            float2 oa, ob;
            oa.x = acc[mt][nt][0] + bias_r[nt].x - ma.x;
            oa.y = acc[mt][nt][1] + bias_r[nt].y - ma.y;
            ob.x = acc[mt][nt][2] + bias_r[nt].x - mb.x;
            ob.y = acc[mt][nt][3] + bias_r[nt].y - mb.y;
            stcs_f2(out + (size_t)ra * DIM + j, oa);
            stcs_f2(out + (size_t)rb * DIM + j, ob);
        }
    }
}

// ---------------------------------------------------------------------------
extern "C" void kernel_launch(void* const* d_in, const int* in_sizes, int n_in,
                              void* d_out, int out_size) {
    const float* x   = (const float*)d_in[0];
    const int*   seg = (const int*)d_in[1];
    const float* GW = nullptr;
    const float* Gb = nullptr;
    const float* LW = nullptr;
    for (int i = 2; i < n_in; i++) {
        int s = in_sizes[i];
        if (s == DIM * DIM) { if (!GW) GW = (const float*)d_in[i]; else LW = (const float*)d_in[i]; }
        else if (s == DIM) { Gb = (const float*)d_in[i]; }
    }
    float* out = (float*)d_out;

    cudaFuncSetAttribute(k2_xm,   cudaFuncAttributeMaxDynamicSharedMemorySize, 74240);
    cudaFuncSetAttribute(k3_main, cudaFuncAttributeMaxDynamicSharedMemorySize, K3_SMEM);

    k0_init<<<2048, 256>>>(GW);
    k1_segsum<<<NROWS / 1024, 256>>>(x, seg);
    k2_xm<<<NSEG / 16, 128, 74240>>>(LW);
    k3_main<<<NROWS / 128, 256, K3_SMEM>>>(x, seg, Gb, out);
}

// round 11
// speedup vs baseline: 1.2531x; 1.1592x over previous
#include <cuda_runtime.h>
#include <cuda_bf16.h>
#include <cstdint>

#define NROWS 1048576
#define DIM   128
#define NSEG  4096

// Scratch (__device__ globals per allocation-free rule)
__device__ float g_xs[NSEG * DIM];                          // segment sums (2 MB)
__device__ float g_xm[NSEG * DIM];                          // xs @ Lambda^T (2 MB)
__device__ __align__(16) __nv_bfloat16 g_GbI[DIM * 136];    // Gamma bf16, padded-row image

#define ASTRIDE 136                         // halves per smem row (pad 8)
#define K3_SMEM (2 * 128 * ASTRIDE * 2)     // 69632 bytes

__device__ __forceinline__ uint32_t smem_u32(const void* p) {
    uint32_t a;
    asm("{ .reg .u64 t; cvta.to.shared.u64 t, %1; cvt.u32.u64 %0, t; }" : "=r"(a) : "l"(p));
    return a;
}
__device__ __forceinline__ uint32_t pack_bf16x2(float lo, float hi) {
    uint32_t r;
    asm("cvt.rn.bf16x2.f32 %0, %1, %2;" : "=r"(r) : "f"(hi), "f"(lo));
    return r;
}
__device__ __forceinline__ float4 ldcs_f4(const float* p) {
    float4 v;
    asm volatile("ld.global.cs.v4.f32 {%0,%1,%2,%3}, [%4];"
                 : "=f"(v.x), "=f"(v.y), "=f"(v.z), "=f"(v.w) : "l"(p));
    return v;
}
__device__ __forceinline__ void stcs_f2(float* p, float2 v) {
    asm volatile("st.global.cs.v2.f32 [%0], {%1,%2};" :: "l"(p), "f"(v.x), "f"(v.y) : "memory");
}

// ---------------------------------------------------------------------------
// Kernel 0: zero g_xs, build padded-row bf16 image of Gamma [n][k]
// ---------------------------------------------------------------------------
__global__ void k0_init(const float* __restrict__ GW) {
    int idx = blockIdx.x * blockDim.x + threadIdx.x;
    if (idx < NSEG * DIM) g_xs[idx] = 0.0f;
    if (idx < DIM * DIM) {
        int n = idx >> 7, k = idx & 127;
        g_GbI[n * ASTRIDE + k] = __float2bfloat16(GW[idx]);
    }
}

// ---------------------------------------------------------------------------
// Kernel 1: segment sum (sorted ids). Explicit 8-wide load batching: all 8
// (seg, x) loads issue back-to-back (MLP guaranteed), then accumulate with
// run-length regs + boundary atomics. x loads .cs (stream-through L2).
// ---------------------------------------------------------------------------
__global__ __launch_bounds__(256) void k1_segsum(const float* __restrict__ x,
                                                 const int* __restrict__ seg) {
    int t = threadIdx.x;
    int stream = t >> 5;
    int c = (t & 31) * 4;
    int base = blockIdx.x * 1024 + stream;

    float4 acc = make_float4(0.f, 0.f, 0.f, 0.f);
    int cur = seg[base];

    for (int ii = 0; ii < 16; ii++) {
        int s8[8];
        float4 v8[8];
        #pragma unroll
        for (int j = 0; j < 8; j++) {
            int r = base + (ii * 8 + j) * 8;
            s8[j] = seg[r];
            v8[j] = ldcs_f4(x + (size_t)r * DIM + c);
        }
        #pragma unroll
        for (int j = 0; j < 8; j++) {
            if (s8[j] != cur) {
                float* d = g_xs + (size_t)cur * DIM + c;
                atomicAdd(d + 0, acc.x); atomicAdd(d + 1, acc.y);
                atomicAdd(d + 2, acc.z); atomicAdd(d + 3, acc.w);
                acc = make_float4(0.f, 0.f, 0.f, 0.f);
                cur = s8[j];
            }
            acc.x += v8[j].x; acc.y += v8[j].y;
            acc.z += v8[j].z; acc.w += v8[j].w;
        }
    }
    float* d = g_xs + (size_t)cur * DIM + c;
    atomicAdd(d + 0, acc.x); atomicAdd(d + 1, acc.y);
    atomicAdd(d + 2, acc.z); atomicAdd(d + 3, acc.w);
}

// ---------------------------------------------------------------------------
// Kernel 2: g_xm = g_xs @ Lambda_W^T (fp32 exact)
// ---------------------------------------------------------------------------
__global__ __launch_bounds__(128) void k2_xm(const float* __restrict__ LW) {
    extern __shared__ float sm2[];
    float* Lt  = sm2;                 // [128][129]
    float* xss = sm2 + 128 * 129;     // [16][128]
    int t = threadIdx.x;
    int R0 = blockIdx.x * 16;

    for (int i = 0; i < 128; i++) {
        int e = i * 128 + t;
        int j = e >> 7, k = e & 127;
        Lt[k * 129 + j] = LW[e];
    }
    for (int i = 0; i < 16; i++) {
        int e = i * 128 + t;
        int r = e >> 7, k = e & 127;
        xss[r * 128 + k] = g_xs[(size_t)(R0 + r) * DIM + k];
    }
    __syncthreads();

    float acc[16];
    #pragma unroll
    for (int r = 0; r < 16; r++) acc[r] = 0.f;
    for (int k = 0; k < 128; k++) {
        float lv = Lt[k * 129 + t];
        #pragma unroll
        for (int r = 0; r < 16; r++) acc[r] += xss[r * 128 + k] * lv;
    }
    #pragma unroll
    for (int r = 0; r < 16; r++)
        g_xm[(size_t)(R0 + r) * DIM + t] = acc[r];
}

// ---------------------------------------------------------------------------
// Kernel 3: out = x @ Gamma^T (bf16 HMMA) + bias - xm[seg]
// R6 structure (best measured): 256 thr = 8 warps of 32x64 tiles, smem-staged
// A and B, ldmatrix fragments. NEW: .cs on x staging loads and out stores.
// ---------------------------------------------------------------------------
__global__ __launch_bounds__(256, 2) void k3_main(const float* __restrict__ x,
                                                  const int* __restrict__ seg,
                                                  const float* __restrict__ bias,
                                                  float* __restrict__ out) {
    extern __shared__ __nv_bfloat16 sm3[];
    __nv_bfloat16* As = sm3;                       // [128][136]
    __nv_bfloat16* Bs = sm3 + 128 * ASTRIDE;       // [128][136]  Bs[n][k]

    int tid  = threadIdx.x;
    int warp = tid >> 5;
    int lane = tid & 31;
    int r0 = blockIdx.x * 128;
    int m0 = (warp & 3) * 32;
    int n0 = (warp >> 2) * 64;
    uint32_t sbB = smem_u32(Bs);
    uint32_t sbA = smem_u32(As);

    // Stage B via flat cp.async of padded image (34816 B)
    #pragma unroll
    for (int i = 0; i < 9; i++) {
        int e = i * 256 + tid;
        if (e < (128 * ASTRIDE * 2) / 16)
            asm volatile("cp.async.cg.shared.global [%0], [%1], 16;"
                         :: "r"(sbB + e * 16),
                            "l"((const char*)g_GbI + e * 16) : "memory");
    }
    asm volatile("cp.async.commit_group;" ::: "memory");

    // Stage A: LDG.cs fp32 -> bf16 -> STS.128
    #pragma unroll
    for (int i = 0; i < 8; i++) {
        int e = i * 256 + tid;
        int row = e >> 4, g2 = e & 15;
        const float* src = x + (size_t)(r0 + row) * DIM + g2 * 8;
        float4 v0 = ldcs_f4(src);
        float4 v1 = ldcs_f4(src + 4);
        uint32_t p0 = pack_bf16x2(v0.x, v0.y);
        uint32_t p1 = pack_bf16x2(v0.z, v0.w);
        uint32_t p2 = pack_bf16x2(v1.x, v1.y);
        uint32_t p3 = pack_bf16x2(v1.z, v1.w);
        asm volatile("st.shared.v4.b32 [%0], {%1,%2,%3,%4};"
                     :: "r"(sbA + (row * ASTRIDE + g2 * 8) * 2),
                        "r"(p0), "r"(p1), "r"(p2), "r"(p3) : "memory");
    }

    // Prefetch epilogue seg ids (4 rows/lane)
    int g  = lane >> 2;
    int t4 = lane & 3;
    int sa[2], sb2[2];
    #pragma unroll
    for (int mt = 0; mt < 2; mt++) {
        int ra = r0 + m0 + mt * 16 + g;
        sa[mt]  = seg[ra];
        sb2[mt] = seg[ra + 8];
    }

    asm volatile("cp.async.wait_group 0;" ::: "memory");
    __syncthreads();

    // Fragment base addresses
    uint32_t aoff[2];
    #pragma unroll
    for (int mt = 0; mt < 2; mt++)
        aoff[mt] = sbA + ((m0 + mt * 16 + (lane & 15)) * ASTRIDE + ((lane >> 4) << 3)) * 2;
    uint32_t boff = sbB + ((n0 + (lane & 7) + ((lane >> 4) << 3)) * ASTRIDE
                           + (((lane >> 3) & 1) << 3)) * 2;

    float acc[2][8][4];
    #pragma unroll
    for (int mt = 0; mt < 2; mt++)
        #pragma unroll
        for (int nt = 0; nt < 8; nt++)
            #pragma unroll
            for (int q = 0; q < 4; q++) acc[mt][nt][q] = 0.f;

    #pragma unroll
    for (int ks = 0; ks < 8; ks++) {
        uint32_t a[2][4], b[4][4];
        #pragma unroll
        for (int mt = 0; mt < 2; mt++) {
            asm volatile(
                "ldmatrix.sync.aligned.m8n8.x4.shared.b16 {%0,%1,%2,%3}, [%4];"
                : "=r"(a[mt][0]), "=r"(a[mt][1]), "=r"(a[mt][2]), "=r"(a[mt][3])
                : "r"(aoff[mt] + ks * 32));
        }
        #pragma unroll
        for (int np = 0; np < 4; np++) {
            asm volatile(
                "ldmatrix.sync.aligned.m8n8.x4.shared.b16 {%0,%1,%2,%3}, [%4];"
                : "=r"(b[np][0]), "=r"(b[np][1]), "=r"(b[np][2]), "=r"(b[np][3])
                : "r"(boff + (np * 16 * ASTRIDE) * 2 + ks * 32));
        }
        #pragma unroll
        for (int mt = 0; mt < 2; mt++)
            #pragma unroll
            for (int np = 0; np < 4; np++) {
                asm volatile(
                    "mma.sync.aligned.m16n8k16.row.col.f32.bf16.bf16.f32 "
                    "{%0,%1,%2,%3}, {%4,%5,%6,%7}, {%8,%9}, {%0,%1,%2,%3};\n"
                    : "+f"(acc[mt][2 * np][0]), "+f"(acc[mt][2 * np][1]),
                      "+f"(acc[mt][2 * np][2]), "+f"(acc[mt][2 * np][3])
                    : "r"(a[mt][0]), "r"(a[mt][1]), "r"(a[mt][2]), "r"(a[mt][3]),
                      "r"(b[np][0]), "r"(b[np][1]));
                asm volatile(
                    "mma.sync.aligned.m16n8k16.row.col.f32.bf16.bf16.f32 "
                    "{%0,%1,%2,%3}, {%4,%5,%6,%7}, {%8,%9}, {%0,%1,%2,%3};\n"
                    : "+f"(acc[mt][2 * np + 1][0]), "+f"(acc[mt][2 * np + 1][1]),
                      "+f"(acc[mt][2 * np + 1][2]), "+f"(acc[mt][2 * np + 1][3])
                    : "r"(a[mt][0]), "r"(a[mt][1]), "r"(a[mt][2]), "r"(a[mt][3]),
                      "r"(b[np][2]), "r"(b[np][3]));
            }
    }

    // Epilogue: + bias - xm[seg]; sector-aligned .cs float2 stores
    float2 bias_r[8];
    #pragma unroll
    for (int nt = 0; nt < 8; nt++)
        bias_r[nt] = *(const float2*)(bias + n0 + nt * 8 + 2 * t4);

    #pragma unroll
    for (int mt = 0; mt < 2; mt++) {
        const float* xa = g_xm + (size_t)sa[mt] * DIM;
        const float* xb = g_xm + (size_t)sb2[mt] * DIM;
        int ra = r0 + m0 + mt * 16 + g;
        int rb = ra + 8;
        #pragma unroll
        for (int nt = 0; nt < 8; nt++) {
            int j = n0 + nt * 8 + 2 * t4;
            float2 ma = *(const float2*)(xa + j);
            float2 mb = *(const float2*)(xb + j);
            float2 oa, ob;
            oa.x = acc[mt][nt][0] + bias_r[nt].x - ma.x;
            oa.y = acc[mt][nt][1] + bias_r[nt].y - ma.y;
            ob.x = acc[mt][nt][2] + bias_r[nt].x - mb.x;
            ob.y = acc[mt][nt][3] + bias_r[nt].y - mb.y;
            stcs_f2(out + (size_t)ra * DIM + j, oa);
            stcs_f2(out + (size_t)rb * DIM + j, ob);
        }
    }
}

// ---------------------------------------------------------------------------
extern "C" void kernel_launch(void* const* d_in, const int* in_sizes, int n_in,
                              void* d_out, int out_size) {
    const float* x   = (const float*)d_in[0];
    const int*   seg = (const int*)d_in[1];
    const float* GW = nullptr;
    const float* Gb = nullptr;
    const float* LW = nullptr;
    for (int i = 2; i < n_in; i++) {
        int s = in_sizes[i];
        if (s == DIM * DIM) { if (!GW) GW = (const float*)d_in[i]; else LW = (const float*)d_in[i]; }
        else if (s == DIM) { Gb = (const float*)d_in[i]; }
    }
    float* out = (float*)d_out;

    cudaFuncSetAttribute(k2_xm,   cudaFuncAttributeMaxDynamicSharedMemorySize, 74240);
    cudaFuncSetAttribute(k3_main, cudaFuncAttributeMaxDynamicSharedMemorySize, K3_SMEM);

    k0_init<<<2048, 256>>>(GW);
    k1_segsum<<<NROWS / 1024, 256>>>(x, seg);
    k2_xm<<<NSEG / 16, 128, 74240>>>(LW);
    k3_main<<<NROWS / 128, 256, K3_SMEM>>>(x, seg, Gb, out);
}